// round 1
// baseline (speedup 1.0000x reference)
#include <cuda_runtime.h>
#include <stdint.h>

#define BATCH 16
#define Hdim 1024
#define Wdim 1024
#define NPB (Hdim*Wdim)
#define KTHR 104857          /* int((1.0-0.9)*1048576) with python float semantics */
#define TOPK 5
#define CAND_CAP 65536       /* >= max possible 9x9 local maxima per 1024^2 (ceil(1024/5)^2=42025) */

#define TX 128
#define TY 32
#define HALO 4
#define INW (TX + 2*HALO)    /* 136 */
#define INH (TY + 2*HALO)    /* 40  */
#define PIN 140              /* padded pitch for input tile  */
#define PRM 132              /* padded pitch for rowmax tile */

/* ------------ scratch (static device globals: no allocations) ------------- */
__device__ unsigned int       g_hist[BATCH][4096];
__device__ unsigned long long g_argmax[BATCH];
__device__ unsigned long long g_cand[BATCH][CAND_CAP];
__device__ unsigned int       g_cand_cnt[BATCH];
__device__ unsigned int       g_selbin[BATCH];
__device__ unsigned int       g_rank[BATCH];
__device__ float              g_inbin[BATCH][NPB];     /* worst case: whole map in one bin */
__device__ unsigned int       g_inbin_cnt[BATCH];
__device__ float              g_thr[BATCH];

/* monotone order-preserving float<->uint transform */
__device__ __forceinline__ unsigned int fordu(float f) {
    unsigned int u = __float_as_uint(f);
    return u ^ (unsigned int)(((int)u >> 31) | (int)0x80000000);
}
__device__ __forceinline__ float fordu_inv(unsigned int v) {
    unsigned int u = (v & 0x80000000u) ? (v ^ 0x80000000u) : ~v;
    return __uint_as_float(u);
}
__device__ __forceinline__ unsigned long long umax64(unsigned long long a, unsigned long long b) {
    return a > b ? a : b;
}
#define NEG_INF __int_as_float(0xff800000)

/* ------------------------------- K0: zero -------------------------------- */
__global__ void k0_zero() {
    int tid = blockIdx.x * blockDim.x + threadIdx.x;
    if (tid < BATCH * 4096) ((unsigned int*)g_hist)[tid] = 0u;
    if (tid < BATCH) {
        g_cand_cnt[tid]  = 0u;
        g_inbin_cnt[tid] = 0u;
        g_argmax[tid]    = 0ull;
    }
}

/* --------- K1: max filter + peak candidates + histogram + argmax ---------- */
__global__ __launch_bounds__(256) void k1_main(const float* __restrict__ in) {
    __shared__ float s_in[INH * PIN];
    __shared__ float s_rm[INH * PRM];
    __shared__ unsigned long long s_red[8];
    unsigned int* s_hist = (unsigned int*)s_rm;   /* reused AFTER vpass */

    const int b   = blockIdx.z;
    const int tx0 = blockIdx.x * TX;
    const int ty0 = blockIdx.y * TY;
    const float* base = in + (size_t)b * NPB;
    const int tid  = threadIdx.x;
    const int lane = tid & 31;
    const int wid  = tid >> 5;

    /* load tile + halo (OOB -> -inf, matching reduce_window's -inf init) */
    for (int r = wid; r < INH; r += 8) {
        int gy = ty0 + r - HALO;
        for (int c = lane; c < INW; c += 32) {
            int gx = tx0 + c - HALO;
            float v = NEG_INF;
            if ((unsigned)gy < (unsigned)Hdim && (unsigned)gx < (unsigned)Wdim)
                v = base[gy * Wdim + gx];
            s_in[r * PIN + c] = v;
        }
    }
    __syncthreads();

    /* horizontal 9-window max: 40 rows x 16 chunks of 8 outputs */
    for (int c = tid; c < INH * (TX / 8); c += 256) {
        int r  = c >> 4;
        int xc = (c & 15) << 3;
        const float* row = &s_in[r * PIN + xc];
        float t[16];
        #pragma unroll
        for (int i = 0; i < 16; i++) t[i] = row[i];
        float m2[15], m4[13], m8[9];
        #pragma unroll
        for (int i = 0; i < 15; i++) m2[i] = fmaxf(t[i], t[i + 1]);
        #pragma unroll
        for (int i = 0; i < 13; i++) m4[i] = fmaxf(m2[i], m2[i + 2]);
        #pragma unroll
        for (int i = 0; i < 9; i++)  m8[i] = fmaxf(m4[i], m4[i + 4]);
        float* orow = &s_rm[r * PRM + xc];
        #pragma unroll
        for (int j = 0; j < 8; j++)  orow[j] = fmaxf(m8[j], t[j + 8]);
    }
    __syncthreads();

    /* vertical 9-window max + peak detect: 4 row-chunks x 128 cols */
    for (int c = tid; c < (TY / 8) * TX; c += 256) {
        int x  = c & 127;
        int yc = (c >> 7) << 3;
        float t[16];
        #pragma unroll
        for (int i = 0; i < 16; i++) t[i] = s_rm[(yc + i) * PRM + x];
        float m2[15], m4[13], m8[9];
        #pragma unroll
        for (int i = 0; i < 15; i++) m2[i] = fmaxf(t[i], t[i + 1]);
        #pragma unroll
        for (int i = 0; i < 13; i++) m4[i] = fmaxf(m2[i], m2[i + 2]);
        #pragma unroll
        for (int i = 0; i < 9; i++)  m8[i] = fmaxf(m4[i], m4[i + 4]);
        #pragma unroll
        for (int j = 0; j < 8; j++) {
            float lm = fmaxf(m8[j], t[j + 8]);
            float v  = s_in[(yc + j + HALO) * PIN + x + HALO];
            if (v == lm) {
                unsigned int gy = (unsigned)(ty0 + yc + j);
                unsigned int gx = (unsigned)(tx0 + x);
                unsigned int idx = gy * Wdim + gx;
                unsigned long long key =
                    ((unsigned long long)fordu(v) << 32) | (unsigned long long)(0xFFFFFFFFu - idx);
                unsigned int p = atomicAdd(&g_cand_cnt[b], 1u);
                if (p < CAND_CAP) g_cand[b][p] = key;
            }
        }
    }
    __syncthreads();   /* vpass done: safe to reuse s_rm as histogram */

    for (int i = tid; i < 4096; i += 256) s_hist[i] = 0u;
    __syncthreads();

    unsigned long long lkey = 0ull;
    for (int c = tid; c < TX * TY; c += 256) {
        int x = c & 127, y = c >> 7;
        float v = s_in[(y + HALO) * PIN + x + HALO];
        unsigned int fo = fordu(v);
        atomicAdd(&s_hist[fo >> 20], 1u);
        unsigned int idx = (unsigned)(ty0 + y) * Wdim + (unsigned)(tx0 + x);
        unsigned long long key =
            ((unsigned long long)fo << 32) | (unsigned long long)(0xFFFFFFFFu - idx);
        lkey = umax64(lkey, key);
    }
    #pragma unroll
    for (int o = 16; o; o >>= 1) lkey = umax64(lkey, __shfl_xor_sync(0xFFFFFFFFu, lkey, o));
    if (lane == 0) s_red[wid] = lkey;
    __syncthreads();
    if (tid == 0) {
        unsigned long long m = s_red[0];
        #pragma unroll
        for (int w = 1; w < 8; w++) m = umax64(m, s_red[w]);
        atomicMax(&g_argmax[b], m);
    }
    for (int i = tid; i < 4096; i += 256) {
        unsigned int v = s_hist[i];
        if (v) atomicAdd(&g_hist[b][i], v);
    }
}

/* ------------- K2: find 12-bit bin containing descending rank KTHR -------- */
__global__ void k2_findbin() {
    const int b = blockIdx.x;
    const int tid = threadIdx.x;
    __shared__ unsigned int s_sum[256];
    __shared__ unsigned int s_pref[256];
    /* descending chunk j covers bins [4095-16j .. 4080-16j] */
    unsigned int s = 0;
    int hi = 4095 - 16 * tid;
    #pragma unroll
    for (int i = 0; i < 16; i++) s += g_hist[b][hi - i];
    s_sum[tid] = s;
    __syncthreads();
    if (tid == 0) {
        unsigned int acc = 0;
        for (int j = 0; j < 256; j++) { s_pref[j] = acc; acc += s_sum[j]; }
    }
    __syncthreads();
    if (s_pref[tid] < (unsigned)KTHR && (unsigned)KTHR <= s_pref[tid] + s_sum[tid]) {
        unsigned int rem = (unsigned)KTHR - s_pref[tid];
        int hi2 = 4095 - 16 * tid;
        for (int i = 0; i < 16; i++) {
            unsigned int c = g_hist[b][hi2 - i];
            if (rem <= c) { g_selbin[b] = (unsigned)(hi2 - i); g_rank[b] = rem; break; }
            rem -= c;
        }
    }
}

/* ------------------ K3: compact elements of selected bin ------------------ */
__global__ __launch_bounds__(256) void k3_compact(const float* __restrict__ in) {
    const int b = blockIdx.y;
    const unsigned int selbin = g_selbin[b];
    const float4* base = (const float4*)(in + (size_t)b * NPB);
    int i = blockIdx.x * 256 + threadIdx.x;
    float4 v = base[i];
    float a0 = v.x, a1 = v.y, a2 = v.z, a3 = v.w;
    float a[4] = {a0, a1, a2, a3};
    #pragma unroll
    for (int j = 0; j < 4; j++) {
        if ((fordu(a[j]) >> 20) == selbin) {
            unsigned int p = atomicAdd(&g_inbin_cnt[b], 1u);
            g_inbin[b][p] = a[j];
        }
    }
}

/* -------- K4: refine low 20 bits (12 then 8) -> exact threshold ----------- */
__global__ __launch_bounds__(256) void k4_refine() {
    const int b = blockIdx.x;
    const int tid = threadIdx.x;
    __shared__ unsigned int s_hist[4096];
    __shared__ unsigned int s_sum[256];
    __shared__ unsigned int s_pref[256];
    __shared__ unsigned int s_sel, s_rank2;

    const unsigned int cnt  = g_inbin_cnt[b];
    const unsigned int rank = g_rank[b];

    for (int i = tid; i < 4096; i += 256) s_hist[i] = 0u;
    __syncthreads();
    for (unsigned int i = tid; i < cnt; i += 256) {
        unsigned int fo = fordu(g_inbin[b][i]);
        atomicAdd(&s_hist[(fo >> 8) & 0xFFFu], 1u);
    }
    __syncthreads();
    {
        unsigned int s = 0;
        int hi = 4095 - 16 * tid;
        #pragma unroll
        for (int i = 0; i < 16; i++) s += s_hist[hi - i];
        s_sum[tid] = s;
        __syncthreads();
        if (tid == 0) {
            unsigned int acc = 0;
            for (int j = 0; j < 256; j++) { s_pref[j] = acc; acc += s_sum[j]; }
        }
        __syncthreads();
        if (s_pref[tid] < rank && rank <= s_pref[tid] + s_sum[tid]) {
            unsigned int rem = rank - s_pref[tid];
            int hi2 = 4095 - 16 * tid;
            for (int i = 0; i < 16; i++) {
                unsigned int c = s_hist[hi2 - i];
                if (rem <= c) { s_sel = (unsigned)(hi2 - i); s_rank2 = rem; break; }
                rem -= c;
            }
        }
    }
    __syncthreads();
    const unsigned int sub = s_sel, rank2 = s_rank2;
    __syncthreads();

    if (tid < 256) s_hist[tid] = 0u;
    __syncthreads();
    for (unsigned int i = tid; i < cnt; i += 256) {
        unsigned int fo = fordu(g_inbin[b][i]);
        if (((fo >> 8) & 0xFFFu) == sub) atomicAdd(&s_hist[fo & 0xFFu], 1u);
    }
    __syncthreads();
    if (tid == 0) {
        unsigned int rem = rank2;
        int bin = 255;
        for (; bin >= 0; bin--) {
            unsigned int c = s_hist[bin];
            if (rem <= c) break;
            rem -= c;
        }
        unsigned int fo = (g_selbin[b] << 20) | (sub << 8) | (unsigned int)bin;
        g_thr[b] = fordu_inv(fo);
    }
}

/* --------------- K5: per-batch top-5 + final output assembly -------------- */
__global__ __launch_bounds__(512) void k5_topk(float* __restrict__ out) {
    const int b = blockIdx.x;
    const int tid = threadIdx.x;
    __shared__ unsigned long long s_arr[512];
    __shared__ unsigned long long s_top[TOPK];

    unsigned int cnt = g_cand_cnt[b];
    if (cnt > CAND_CAP) cnt = CAND_CAP;
    const unsigned int thr_ord = fordu(g_thr[b]);

    unsigned long long loc[TOPK];
    #pragma unroll
    for (int j = 0; j < TOPK; j++) loc[j] = 0ull;
    for (unsigned int i = tid; i < cnt; i += 512) {
        unsigned long long k = g_cand[b][i];
        if ((unsigned int)(k >> 32) > thr_ord) {
            if (k > loc[TOPK - 1]) {
                loc[TOPK - 1] = k;
                #pragma unroll
                for (int j = TOPK - 1; j > 0; j--) {
                    if (loc[j] > loc[j - 1]) {
                        unsigned long long t = loc[j - 1]; loc[j - 1] = loc[j]; loc[j] = t;
                    }
                }
            }
        }
    }

    int ptr = 0;
    for (int r = 0; r < TOPK; r++) {
        s_arr[tid] = (ptr < TOPK) ? loc[ptr] : 0ull;
        __syncthreads();
        for (int o = 256; o; o >>= 1) {
            if (tid < o) s_arr[tid] = umax64(s_arr[tid], s_arr[tid + o]);
            __syncthreads();
        }
        unsigned long long w = s_arr[0];
        __syncthreads();
        if (tid == 0) s_top[r] = w;
        if (ptr < TOPK && loc[ptr] == w && w != 0ull) ptr++;
        __syncthreads();
    }

    if (tid == 0) {
        float topv[TOPK], xs[TOPK], ys[TOPK];
        bool hp[TOPK];
        #pragma unroll
        for (int j = 0; j < TOPK; j++) {
            unsigned long long k = s_top[j];
            hp[j] = (k != 0ull);
            topv[j] = hp[j] ? fordu_inv((unsigned int)(k >> 32)) : NEG_INF;
            unsigned int idx = 0xFFFFFFFFu - (unsigned int)(k & 0xFFFFFFFFull);
            xs[j] = (float)(idx % Wdim);
            ys[j] = (float)(idx / Wdim);
        }
        bool has_any = hp[0];
        if (!has_any) {
            unsigned int fidx = 0xFFFFFFFFu - (unsigned int)(g_argmax[b] & 0xFFFFFFFFull);
            xs[0] = (float)(fidx % Wdim);
            ys[0] = (float)(fidx / Wdim);
        }
        float peak_max = topv[0];
        int n_valid = 0;
        #pragma unroll
        for (int j = 0; j < TOPK; j++)
            if (topv[j] >= peak_max * 0.5f && hp[j]) n_valid++;
        if (n_valid < 1) n_valid = 1;
        #pragma unroll
        for (int j = 0; j < TOPK; j++) {
            bool keep = (j < n_valid);
            out[b * (TOPK * 2) + 2 * j + 0] = keep ? xs[j] : -1.0f;
            out[b * (TOPK * 2) + 2 * j + 1] = keep ? ys[j] : -1.0f;
            out[BATCH * TOPK * 2 + b * TOPK + j] = keep ? 1.0f : -1.0f;
        }
    }
}

/* -------------------------------- launch ---------------------------------- */
extern "C" void kernel_launch(void* const* d_in, const int* in_sizes, int n_in,
                              void* d_out, int out_size) {
    const float* in = (const float*)d_in[0];
    float* out = (float*)d_out;
    (void)in_sizes; (void)n_in; (void)out_size;

    k0_zero<<<256, 256>>>();
    k1_main<<<dim3(Wdim / TX, Hdim / TY, BATCH), 256>>>(in);
    k2_findbin<<<BATCH, 256>>>();
    k3_compact<<<dim3(NPB / 4 / 256, BATCH), 256>>>(in);
    k4_refine<<<BATCH, 256>>>();
    k5_topk<<<BATCH, 512>>>(out);
}

// round 2
// speedup vs baseline: 2.4739x; 2.4739x over previous
#include <cuda_runtime.h>
#include <stdint.h>

#define BATCH 16
#define Hdim 1024
#define Wdim 1024
#define NPB (Hdim*Wdim)
#define KTHR 104857          /* int((1.0-0.9)*1048576) with python float semantics */
#define TOPK 5
#define CAND_CAP 65536

#define TX 128
#define TY 32
#define HALO 4
#define INW (TX + 2*HALO)    /* 136 */
#define INH (TY + 2*HALO)    /* 40  */
#define PIN 140
#define PRM 132
#define CBUF 512             /* per-block candidate buffer */

/* ------------ scratch (static device globals: no allocations) ------------- */
__device__ unsigned int       g_hist[BATCH][4096];
__device__ unsigned long long g_argmax[BATCH];
__device__ unsigned long long g_cand[BATCH][CAND_CAP];
__device__ unsigned int       g_cand_cnt[BATCH];
__device__ unsigned int       g_selbin[BATCH];
__device__ unsigned int       g_rank[BATCH];
__device__ float              g_inbin[BATCH][NPB];
__device__ unsigned int       g_inbin_cnt[BATCH];
__device__ float              g_thr[BATCH];

__device__ __forceinline__ unsigned int fordu(float f) {
    unsigned int u = __float_as_uint(f);
    return u ^ (unsigned int)(((int)u >> 31) | (int)0x80000000);
}
__device__ __forceinline__ float fordu_inv(unsigned int v) {
    unsigned int u = (v & 0x80000000u) ? (v ^ 0x80000000u) : ~v;
    return __uint_as_float(u);
}
__device__ __forceinline__ unsigned long long umax64(unsigned long long a, unsigned long long b) {
    return a > b ? a : b;
}
#define NEG_INF __int_as_float(0xff800000)

/* ------------------------------- K0: zero -------------------------------- */
__global__ void k0_zero() {
    int tid = blockIdx.x * blockDim.x + threadIdx.x;
    if (tid < BATCH * 4096) ((unsigned int*)g_hist)[tid] = 0u;
    if (tid < BATCH) {
        g_cand_cnt[tid]  = 0u;
        g_inbin_cnt[tid] = 0u;
        g_argmax[tid]    = 0ull;
    }
}

/* --------- K1: max filter + peak candidates + histogram + argmax ---------- */
__global__ __launch_bounds__(256) void k1_main(const float* __restrict__ in) {
    __shared__ float s_in[INH * PIN];
    __shared__ float s_rm[INH * PRM];
    __shared__ unsigned long long s_red[8];
    __shared__ unsigned long long s_cbuf[CBUF];
    __shared__ unsigned int s_ccnt, s_cbase, s_cn;
    unsigned int* s_hist = (unsigned int*)s_rm;   /* reused AFTER vpass */

    const int b   = blockIdx.z;
    const int tx0 = blockIdx.x * TX;
    const int ty0 = blockIdx.y * TY;
    const float* base = in + (size_t)b * NPB;
    const int tid  = threadIdx.x;
    const int lane = tid & 31;
    const int wid  = tid >> 5;

    if (tid == 0) s_ccnt = 0u;

    /* load tile + halo (OOB -> -inf) */
    for (int r = wid; r < INH; r += 8) {
        int gy = ty0 + r - HALO;
        for (int c = lane; c < INW; c += 32) {
            int gx = tx0 + c - HALO;
            float v = NEG_INF;
            if ((unsigned)gy < (unsigned)Hdim && (unsigned)gx < (unsigned)Wdim)
                v = base[gy * Wdim + gx];
            s_in[r * PIN + c] = v;
        }
    }
    __syncthreads();

    /* horizontal 9-window max */
    for (int c = tid; c < INH * (TX / 8); c += 256) {
        int r  = c >> 4;
        int xc = (c & 15) << 3;
        const float* row = &s_in[r * PIN + xc];
        float t[16];
        #pragma unroll
        for (int i = 0; i < 16; i++) t[i] = row[i];
        float m2[15], m4[13], m8[9];
        #pragma unroll
        for (int i = 0; i < 15; i++) m2[i] = fmaxf(t[i], t[i + 1]);
        #pragma unroll
        for (int i = 0; i < 13; i++) m4[i] = fmaxf(m2[i], m2[i + 2]);
        #pragma unroll
        for (int i = 0; i < 9; i++)  m8[i] = fmaxf(m4[i], m4[i + 4]);
        float* orow = &s_rm[r * PRM + xc];
        #pragma unroll
        for (int j = 0; j < 8; j++)  orow[j] = fmaxf(m8[j], t[j + 8]);
    }
    __syncthreads();

    /* vertical 9-window max + peak detect -> SMEM candidate buffer */
    for (int c = tid; c < (TY / 8) * TX; c += 256) {
        int x  = c & 127;
        int yc = (c >> 7) << 3;
        float t[16];
        #pragma unroll
        for (int i = 0; i < 16; i++) t[i] = s_rm[(yc + i) * PRM + x];
        float m2[15], m4[13], m8[9];
        #pragma unroll
        for (int i = 0; i < 15; i++) m2[i] = fmaxf(t[i], t[i + 1]);
        #pragma unroll
        for (int i = 0; i < 13; i++) m4[i] = fmaxf(m2[i], m2[i + 2]);
        #pragma unroll
        for (int i = 0; i < 9; i++)  m8[i] = fmaxf(m4[i], m4[i + 4]);
        #pragma unroll
        for (int j = 0; j < 8; j++) {
            float lm = fmaxf(m8[j], t[j + 8]);
            float v  = s_in[(yc + j + HALO) * PIN + x + HALO];
            if (v == lm) {
                unsigned int idx = (unsigned)(ty0 + yc + j) * Wdim + (unsigned)(tx0 + x);
                unsigned long long key =
                    ((unsigned long long)fordu(v) << 32) | (unsigned long long)(0xFFFFFFFFu - idx);
                unsigned int p = atomicAdd(&s_ccnt, 1u);
                if (p < CBUF) s_cbuf[p] = key;
                else {  /* practically never: ties only */
                    unsigned int q = atomicAdd(&g_cand_cnt[b], 1u);
                    if (q < CAND_CAP) g_cand[b][q] = key;
                }
            }
        }
    }
    __syncthreads();

    /* flush candidate buffer: ONE contended global atomic per block */
    if (tid == 0) {
        unsigned int n = s_ccnt < CBUF ? s_ccnt : CBUF;
        s_cn = n;
        s_cbase = atomicAdd(&g_cand_cnt[b], n);
    }
    __syncthreads();
    for (unsigned int i = tid; i < s_cn; i += 256) {
        unsigned int q = s_cbase + i;
        if (q < CAND_CAP) g_cand[b][q] = s_cbuf[i];
    }
    __syncthreads();   /* safe to reuse s_rm as histogram */

    for (int i = tid; i < 4096; i += 256) s_hist[i] = 0u;
    __syncthreads();

    unsigned long long lkey = 0ull;
    for (int c = tid; c < TX * TY; c += 256) {
        int x = c & 127, y = c >> 7;
        float v = s_in[(y + HALO) * PIN + x + HALO];
        unsigned int fo = fordu(v);
        atomicAdd(&s_hist[fo >> 20], 1u);
        unsigned int idx = (unsigned)(ty0 + y) * Wdim + (unsigned)(tx0 + x);
        unsigned long long key =
            ((unsigned long long)fo << 32) | (unsigned long long)(0xFFFFFFFFu - idx);
        lkey = umax64(lkey, key);
    }
    #pragma unroll
    for (int o = 16; o; o >>= 1) lkey = umax64(lkey, __shfl_xor_sync(0xFFFFFFFFu, lkey, o));
    if (lane == 0) s_red[wid] = lkey;
    __syncthreads();
    if (tid == 0) {
        unsigned long long m = s_red[0];
        #pragma unroll
        for (int w = 1; w < 8; w++) m = umax64(m, s_red[w]);
        atomicMax(&g_argmax[b], m);   /* no return use -> RED */
    }
    for (int i = tid; i < 4096; i += 256) {
        unsigned int v = s_hist[i];
        if (v) atomicAdd(&g_hist[b][i], v);   /* no return use -> RED, spread addrs */
    }
}

/* ------------- K2: find 12-bit bin containing descending rank KTHR -------- */
__global__ void k2_findbin() {
    const int b = blockIdx.x;
    const int tid = threadIdx.x;
    __shared__ unsigned int s_sum[256];
    __shared__ unsigned int s_pref[256];
    unsigned int s = 0;
    int hi = 4095 - 16 * tid;
    #pragma unroll
    for (int i = 0; i < 16; i++) s += g_hist[b][hi - i];
    s_sum[tid] = s;
    __syncthreads();
    if (tid == 0) {
        unsigned int acc = 0;
        for (int j = 0; j < 256; j++) { s_pref[j] = acc; acc += s_sum[j]; }
    }
    __syncthreads();
    if (s_pref[tid] < (unsigned)KTHR && (unsigned)KTHR <= s_pref[tid] + s_sum[tid]) {
        unsigned int rem = (unsigned)KTHR - s_pref[tid];
        int hi2 = 4095 - 16 * tid;
        for (int i = 0; i < 16; i++) {
            unsigned int c = g_hist[b][hi2 - i];
            if (rem <= c) { g_selbin[b] = (unsigned)(hi2 - i); g_rank[b] = rem; break; }
            rem -= c;
        }
    }
}

/* ------------------ K3: compact elements of selected bin ------------------ */
/* block covers 4096 floats (1024 float4); 4 independent float4 loads/thread */
__global__ __launch_bounds__(256) void k3_compact(const float* __restrict__ in) {
    __shared__ float s_buf[4096];
    __shared__ unsigned int s_cnt, s_base, s_n;

    const int b = blockIdx.y;
    const unsigned int selbin = __ldg(&g_selbin[b]);
    const float4* base = (const float4*)(in + (size_t)b * NPB);
    const int tid = threadIdx.x;
    if (tid == 0) s_cnt = 0u;
    __syncthreads();

    const int blk4 = blockIdx.x * 1024;
    float4 v[4];
    #pragma unroll
    for (int k = 0; k < 4; k++) v[k] = base[blk4 + tid + 256 * k];

    #pragma unroll
    for (int k = 0; k < 4; k++) {
        float a[4] = {v[k].x, v[k].y, v[k].z, v[k].w};
        #pragma unroll
        for (int j = 0; j < 4; j++) {
            if ((fordu(a[j]) >> 20) == selbin) {
                unsigned int p = atomicAdd(&s_cnt, 1u);   /* SMEM atomic */
                s_buf[p] = a[j];                           /* p < 4096 always */
            }
        }
    }
    __syncthreads();

    if (tid == 0) {
        s_n = s_cnt;
        s_base = atomicAdd(&g_inbin_cnt[b], s_cnt);   /* ONE global atomic per block */
    }
    __syncthreads();
    for (unsigned int i = tid; i < s_n; i += 256)
        g_inbin[b][s_base + i] = s_buf[i];
}

/* -------- K4: refine low 20 bits (12 then 8) -> exact threshold ----------- */
__global__ __launch_bounds__(256) void k4_refine() {
    const int b = blockIdx.x;
    const int tid = threadIdx.x;
    __shared__ unsigned int s_hist[4096];
    __shared__ unsigned int s_sum[256];
    __shared__ unsigned int s_pref[256];
    __shared__ unsigned int s_sel, s_rank2;

    const unsigned int cnt  = g_inbin_cnt[b];
    const unsigned int rank = g_rank[b];

    for (int i = tid; i < 4096; i += 256) s_hist[i] = 0u;
    __syncthreads();
    for (unsigned int i = tid; i < cnt; i += 256) {
        unsigned int fo = fordu(g_inbin[b][i]);
        atomicAdd(&s_hist[(fo >> 8) & 0xFFFu], 1u);
    }
    __syncthreads();
    {
        unsigned int s = 0;
        int hi = 4095 - 16 * tid;
        #pragma unroll
        for (int i = 0; i < 16; i++) s += s_hist[hi - i];
        s_sum[tid] = s;
        __syncthreads();
        if (tid == 0) {
            unsigned int acc = 0;
            for (int j = 0; j < 256; j++) { s_pref[j] = acc; acc += s_sum[j]; }
        }
        __syncthreads();
        if (s_pref[tid] < rank && rank <= s_pref[tid] + s_sum[tid]) {
            unsigned int rem = rank - s_pref[tid];
            int hi2 = 4095 - 16 * tid;
            for (int i = 0; i < 16; i++) {
                unsigned int c = s_hist[hi2 - i];
                if (rem <= c) { s_sel = (unsigned)(hi2 - i); s_rank2 = rem; break; }
                rem -= c;
            }
        }
    }
    __syncthreads();
    const unsigned int sub = s_sel, rank2 = s_rank2;
    __syncthreads();

    if (tid < 256) s_hist[tid] = 0u;
    __syncthreads();
    for (unsigned int i = tid; i < cnt; i += 256) {
        unsigned int fo = fordu(g_inbin[b][i]);
        if (((fo >> 8) & 0xFFFu) == sub) atomicAdd(&s_hist[fo & 0xFFu], 1u);
    }
    __syncthreads();
    if (tid == 0) {
        unsigned int rem = rank2;
        int bin = 255;
        for (; bin >= 0; bin--) {
            unsigned int c = s_hist[bin];
            if (rem <= c) break;
            rem -= c;
        }
        unsigned int fo = (g_selbin[b] << 20) | (sub << 8) | (unsigned int)bin;
        g_thr[b] = fordu_inv(fo);
    }
}

/* --------------- K5: per-batch top-5 + final output assembly -------------- */
__global__ __launch_bounds__(512) void k5_topk(float* __restrict__ out) {
    const int b = blockIdx.x;
    const int tid = threadIdx.x;
    __shared__ unsigned long long s_arr[512];
    __shared__ unsigned long long s_top[TOPK];

    unsigned int cnt = g_cand_cnt[b];
    if (cnt > CAND_CAP) cnt = CAND_CAP;
    const unsigned int thr_ord = fordu(g_thr[b]);

    unsigned long long loc[TOPK];
    #pragma unroll
    for (int j = 0; j < TOPK; j++) loc[j] = 0ull;
    for (unsigned int i = tid; i < cnt; i += 512) {
        unsigned long long k = g_cand[b][i];
        if ((unsigned int)(k >> 32) > thr_ord) {
            if (k > loc[TOPK - 1]) {
                loc[TOPK - 1] = k;
                #pragma unroll
                for (int j = TOPK - 1; j > 0; j--) {
                    if (loc[j] > loc[j - 1]) {
                        unsigned long long t = loc[j - 1]; loc[j - 1] = loc[j]; loc[j] = t;
                    }
                }
            }
        }
    }

    int ptr = 0;
    for (int r = 0; r < TOPK; r++) {
        s_arr[tid] = (ptr < TOPK) ? loc[ptr] : 0ull;
        __syncthreads();
        for (int o = 256; o; o >>= 1) {
            if (tid < o) s_arr[tid] = umax64(s_arr[tid], s_arr[tid + o]);
            __syncthreads();
        }
        unsigned long long w = s_arr[0];
        __syncthreads();
        if (tid == 0) s_top[r] = w;
        if (ptr < TOPK && loc[ptr] == w && w != 0ull) ptr++;
        __syncthreads();
    }

    if (tid == 0) {
        float topv[TOPK], xs[TOPK], ys[TOPK];
        bool hp[TOPK];
        #pragma unroll
        for (int j = 0; j < TOPK; j++) {
            unsigned long long k = s_top[j];
            hp[j] = (k != 0ull);
            topv[j] = hp[j] ? fordu_inv((unsigned int)(k >> 32)) : NEG_INF;
            unsigned int idx = 0xFFFFFFFFu - (unsigned int)(k & 0xFFFFFFFFull);
            xs[j] = (float)(idx % Wdim);
            ys[j] = (float)(idx / Wdim);
        }
        bool has_any = hp[0];
        if (!has_any) {
            unsigned int fidx = 0xFFFFFFFFu - (unsigned int)(g_argmax[b] & 0xFFFFFFFFull);
            xs[0] = (float)(fidx % Wdim);
            ys[0] = (float)(fidx / Wdim);
        }
        float peak_max = topv[0];
        int n_valid = 0;
        #pragma unroll
        for (int j = 0; j < TOPK; j++)
            if (topv[j] >= peak_max * 0.5f && hp[j]) n_valid++;
        if (n_valid < 1) n_valid = 1;
        #pragma unroll
        for (int j = 0; j < TOPK; j++) {
            bool keep = (j < n_valid);
            out[b * (TOPK * 2) + 2 * j + 0] = keep ? xs[j] : -1.0f;
            out[b * (TOPK * 2) + 2 * j + 1] = keep ? ys[j] : -1.0f;
            out[BATCH * TOPK * 2 + b * TOPK + j] = keep ? 1.0f : -1.0f;
        }
    }
}

/* -------------------------------- launch ---------------------------------- */
extern "C" void kernel_launch(void* const* d_in, const int* in_sizes, int n_in,
                              void* d_out, int out_size) {
    const float* in = (const float*)d_in[0];
    float* out = (float*)d_out;
    (void)in_sizes; (void)n_in; (void)out_size;

    k0_zero<<<256, 256>>>();
    k1_main<<<dim3(Wdim / TX, Hdim / TY, BATCH), 256>>>(in);
    k2_findbin<<<BATCH, 256>>>();
    k3_compact<<<dim3(NPB / 4096, BATCH), 256>>>(in);
    k4_refine<<<BATCH, 256>>>();
    k5_topk<<<BATCH, 512>>>(out);
}

// round 3
// speedup vs baseline: 2.8587x; 1.1556x over previous
#include <cuda_runtime.h>
#include <stdint.h>

#define BATCH 16
#define Hdim 1024
#define Wdim 1024
#define NPB (Hdim*Wdim)
#define KTHR 104857
#define TOPK 5
#define CAND_CAP 65536

#define TX 128
#define TY 32
#define HALO 4
#define INW (TX + 2*HALO)
#define INH (TY + 2*HALO)
#define PIN 140
#define PRM 132
#define CBUF 512

#define PRE_L2 766u            /* (fordu(v)>>22) for v in [1.0,1.5) */
#define FO_GE15 0xBFC00000u    /* fordu(1.5) */

/* ------------ scratch ------------- */
__device__ unsigned int       g_hist[BATCH][4096];   /* fallback only */
__device__ unsigned long long g_cand[BATCH][CAND_CAP];
__device__ unsigned int       g_cand_cnt[BATCH];
__device__ unsigned int       g_cntS[BATCH];         /* count v>=1.5 */
__device__ unsigned int       g_ctrC[BATCH][32];     /* 32 bins over [1,1.5) */
__device__ int                g_fb[BATCH];
__device__ unsigned int       g_shift[BATCH];
__device__ unsigned int       g_selpre[BATCH];
__device__ unsigned int       g_rank[BATCH];
__device__ float              g_inbin[BATCH][NPB];
__device__ unsigned int       g_inbin_cnt[BATCH];
__device__ float              g_thr[BATCH];

__device__ __forceinline__ unsigned int fordu(float f) {
    unsigned int u = __float_as_uint(f);
    return u ^ (unsigned int)(((int)u >> 31) | (int)0x80000000);
}
__device__ __forceinline__ float fordu_inv(unsigned int v) {
    unsigned int u = (v & 0x80000000u) ? (v ^ 0x80000000u) : ~v;
    return __uint_as_float(u);
}
__device__ __forceinline__ unsigned long long umax64(unsigned long long a, unsigned long long b) {
    return a > b ? a : b;
}
#define NEG_INF __int_as_float(0xff800000)

/* ------------------------------- K0: zero -------------------------------- */
__global__ void k0_zero() {
    int tid = blockIdx.x * blockDim.x + threadIdx.x;
    if (tid < BATCH * 4096) ((unsigned int*)g_hist)[tid] = 0u;
    if (tid < BATCH * 32) ((unsigned int*)g_ctrC)[tid] = 0u;
    if (tid < BATCH) {
        g_cand_cnt[tid]  = 0u;
        g_inbin_cnt[tid] = 0u;
        g_cntS[tid]      = 0u;
    }
}

/* --------- K1: load+count + max filter + peak candidates ---------- */
__global__ __launch_bounds__(256) void k1_main(const float* __restrict__ in) {
    __shared__ float s_in[INH * PIN];
    __shared__ float s_rm[INH * PRM];
    __shared__ unsigned long long s_cbuf[CBUF];
    __shared__ unsigned int s_ccnt, s_cbase, s_cn;
    __shared__ unsigned int s_ctr[32];
    __shared__ unsigned int s_scount;

    const int b   = blockIdx.z;
    const int tx0 = blockIdx.x * TX;
    const int ty0 = blockIdx.y * TY;
    const float* base = in + (size_t)b * NPB;
    const int tid  = threadIdx.x;
    const int lane = tid & 31;
    const int wid  = tid >> 5;

    if (tid < 32) s_ctr[tid] = 0u;
    if (tid == 0) { s_ccnt = 0u; s_scount = 0u; }
    __syncthreads();

    /* load tile + halo; count S and 32 bins of [1,1.5) inline (interior only) */
    unsigned int myS = 0u;
    #pragma unroll
    for (int ri = 0; ri < 5; ri++) {
        int r = wid + ri * 8;
        int gy = ty0 + r - HALO;
        bool rowin = (unsigned)gy < (unsigned)Hdim;
        bool rint  = (r >= HALO) && (r < HALO + TY);
        #pragma unroll
        for (int ci = 0; ci < 5; ci++) {
            int c = lane + ci * 32;
            int gx = tx0 + c - HALO;
            bool inx = (c < INW) && ((unsigned)gx < (unsigned)Wdim);
            float v = NEG_INF;
            if (rowin && inx) v = base[gy * Wdim + gx];
            if (c < INW) s_in[r * PIN + c] = v;
            bool intr = rowin && rint && (c >= HALO) && (c < HALO + TX) && inx;
            unsigned int fo = fordu(v);
            if (intr && fo >= FO_GE15) myS++;
            unsigned int key = (intr && (fo >> 22) == PRE_L2) ? ((fo >> 17) & 31u) : 63u;
            unsigned int mm = __match_any_sync(0xFFFFFFFFu, key);
            if (key != 63u && (mm & ((1u << lane) - 1u)) == 0u)
                atomicAdd(&s_ctr[key], (unsigned)__popc(mm));
        }
    }
    /* reduce S within block */
    #pragma unroll
    for (int o = 16; o; o >>= 1) myS += __shfl_xor_sync(0xFFFFFFFFu, myS, o);
    if (lane == 0 && myS) atomicAdd(&s_scount, myS);
    __syncthreads();

    /* flush counters (cheap global REDs) */
    if (tid == 0 && s_scount) atomicAdd(&g_cntS[b], s_scount);
    if (tid < 32 && s_ctr[tid]) atomicAdd(&g_ctrC[b][tid], s_ctr[tid]);

    /* horizontal 9-window max */
    for (int c = tid; c < INH * (TX / 8); c += 256) {
        int r  = c >> 4;
        int xc = (c & 15) << 3;
        const float* row = &s_in[r * PIN + xc];
        float t[16];
        #pragma unroll
        for (int i = 0; i < 16; i++) t[i] = row[i];
        float m2[15], m4[13], m8[9];
        #pragma unroll
        for (int i = 0; i < 15; i++) m2[i] = fmaxf(t[i], t[i + 1]);
        #pragma unroll
        for (int i = 0; i < 13; i++) m4[i] = fmaxf(m2[i], m2[i + 2]);
        #pragma unroll
        for (int i = 0; i < 9; i++)  m8[i] = fmaxf(m4[i], m4[i + 4]);
        float* orow = &s_rm[r * PRM + xc];
        #pragma unroll
        for (int j = 0; j < 8; j++)  orow[j] = fmaxf(m8[j], t[j + 8]);
    }
    __syncthreads();

    /* vertical 9-window max + peak detect -> SMEM candidate buffer */
    for (int c = tid; c < (TY / 8) * TX; c += 256) {
        int x  = c & 127;
        int yc = (c >> 7) << 3;
        float t[16];
        #pragma unroll
        for (int i = 0; i < 16; i++) t[i] = s_rm[(yc + i) * PRM + x];
        float m2[15], m4[13], m8[9];
        #pragma unroll
        for (int i = 0; i < 15; i++) m2[i] = fmaxf(t[i], t[i + 1]);
        #pragma unroll
        for (int i = 0; i < 13; i++) m4[i] = fmaxf(m2[i], m2[i + 2]);
        #pragma unroll
        for (int i = 0; i < 9; i++)  m8[i] = fmaxf(m4[i], m4[i + 4]);
        #pragma unroll
        for (int j = 0; j < 8; j++) {
            float lm = fmaxf(m8[j], t[j + 8]);
            float v  = s_in[(yc + j + HALO) * PIN + x + HALO];
            if (v == lm) {
                unsigned int idx = (unsigned)(ty0 + yc + j) * Wdim + (unsigned)(tx0 + x);
                unsigned long long key =
                    ((unsigned long long)fordu(v) << 32) | (unsigned long long)(0xFFFFFFFFu - idx);
                unsigned int p = atomicAdd(&s_ccnt, 1u);
                if (p < CBUF) s_cbuf[p] = key;
                else {
                    unsigned int q = atomicAdd(&g_cand_cnt[b], 1u);
                    if (q < CAND_CAP) g_cand[b][q] = key;
                }
            }
        }
    }
    __syncthreads();

    if (tid == 0) {
        unsigned int n = s_ccnt < CBUF ? s_ccnt : CBUF;
        s_cn = n;
        s_cbase = atomicAdd(&g_cand_cnt[b], n);
    }
    __syncthreads();
    for (unsigned int i = tid; i < s_cn; i += 256) {
        unsigned int q = s_cbase + i;
        if (q < CAND_CAP) g_cand[b][q] = s_cbuf[i];
    }
}

/* ---------- K2: locate rank among 32 bins of [1,1.5), else fallback ------- */
__global__ void k2_select() {
    const int b = blockIdx.x;
    __shared__ unsigned int c[32];
    if (threadIdx.x < 32) c[threadIdx.x] = g_ctrC[b][threadIdx.x];
    __syncwarp();
    if (threadIdx.x == 0) {
        unsigned int S = g_cntS[b];
        unsigned int cum = S;
        int sel = -1; unsigned int rem = 0;
        for (int j = 31; j >= 0; j--) {
            if (cum < (unsigned)KTHR && (unsigned)KTHR <= cum + c[j]) {
                sel = j; rem = (unsigned)KTHR - cum; break;
            }
            cum += c[j];
        }
        if (sel < 0) g_fb[b] = 1;
        else {
            g_fb[b] = 0;
            g_shift[b]  = 17u;
            g_selpre[b] = (PRE_L2 << 5) | (unsigned)sel;
            g_rank[b]   = rem;
        }
    }
}

/* --------- KFB1: fallback full 12-bit histogram (early-exit normally) ----- */
__global__ __launch_bounds__(256) void kfb_hist(const float* __restrict__ in) {
    const int b = blockIdx.y;
    if (!g_fb[b]) return;
    __shared__ unsigned int s_hist[4096];
    const int tid = threadIdx.x;
    for (int i = tid; i < 4096; i += 256) s_hist[i] = 0u;
    __syncthreads();
    const float4* base = (const float4*)(in + (size_t)b * NPB);
    const int blk4 = blockIdx.x * 4096;   /* 64 blocks x 4096 float4 */
    for (int k = 0; k < 16; k++) {
        float4 v = base[blk4 + tid + 256 * k];
        atomicAdd(&s_hist[fordu(v.x) >> 20], 1u);
        atomicAdd(&s_hist[fordu(v.y) >> 20], 1u);
        atomicAdd(&s_hist[fordu(v.z) >> 20], 1u);
        atomicAdd(&s_hist[fordu(v.w) >> 20], 1u);
    }
    __syncthreads();
    for (int i = tid; i < 4096; i += 256) {
        unsigned int v = s_hist[i];
        if (v) atomicAdd(&g_hist[b][i], v);
    }
}

/* --------- KFB2: fallback 12-bit bin select (early-exit normally) --------- */
__global__ void kfb_select() {
    const int b = blockIdx.x;
    if (!g_fb[b]) return;
    const int tid = threadIdx.x;
    __shared__ unsigned int s_sum[256];
    __shared__ unsigned int s_pref[256];
    unsigned int s = 0;
    int hi = 4095 - 16 * tid;
    #pragma unroll
    for (int i = 0; i < 16; i++) s += g_hist[b][hi - i];
    s_sum[tid] = s;
    __syncthreads();
    if (tid == 0) {
        unsigned int acc = 0;
        for (int j = 0; j < 256; j++) { s_pref[j] = acc; acc += s_sum[j]; }
    }
    __syncthreads();
    if (s_pref[tid] < (unsigned)KTHR && (unsigned)KTHR <= s_pref[tid] + s_sum[tid]) {
        unsigned int rem = (unsigned)KTHR - s_pref[tid];
        int hi2 = 4095 - 16 * tid;
        for (int i = 0; i < 16; i++) {
            unsigned int c = g_hist[b][hi2 - i];
            if (rem <= c) {
                g_selpre[b] = (unsigned)(hi2 - i);
                g_shift[b]  = 20u;
                g_rank[b]   = rem;
                break;
            }
            rem -= c;
        }
    }
}

/* ------------------ K3: compact elements of selected bin ------------------ */
__global__ __launch_bounds__(256) void k3_compact(const float* __restrict__ in) {
    __shared__ float s_buf[4096];
    __shared__ unsigned int s_cnt, s_base, s_n;

    const int b = blockIdx.y;
    const unsigned int selpre = g_selpre[b];
    const unsigned int shift  = g_shift[b];
    const float4* base = (const float4*)(in + (size_t)b * NPB);
    const int tid = threadIdx.x;
    if (tid == 0) s_cnt = 0u;
    __syncthreads();

    const int blk4 = blockIdx.x * 1024;
    float4 v[4];
    #pragma unroll
    for (int k = 0; k < 4; k++) v[k] = base[blk4 + tid + 256 * k];

    #pragma unroll
    for (int k = 0; k < 4; k++) {
        float a[4] = {v[k].x, v[k].y, v[k].z, v[k].w};
        #pragma unroll
        for (int j = 0; j < 4; j++) {
            if ((fordu(a[j]) >> shift) == selpre) {
                unsigned int p = atomicAdd(&s_cnt, 1u);
                s_buf[p] = a[j];
            }
        }
    }
    __syncthreads();

    if (tid == 0) {
        s_n = s_cnt;
        s_base = atomicAdd(&g_inbin_cnt[b], s_cnt);
    }
    __syncthreads();
    for (unsigned int i = tid; i < s_n; i += 256)
        g_inbin[b][s_base + i] = s_buf[i];
}

/* -------- K4: refine remaining bits (12 then shift-12) -> exact thr ------- */
__global__ __launch_bounds__(256) void k4_refine() {
    const int b = blockIdx.x;
    const int tid = threadIdx.x;
    __shared__ unsigned int s_hist[4096];
    __shared__ unsigned int s_sum[256];
    __shared__ unsigned int s_pref[256];
    __shared__ unsigned int s_sel, s_rank2;

    const unsigned int cnt   = g_inbin_cnt[b];
    const unsigned int rank  = g_rank[b];
    const unsigned int shift = g_shift[b];
    const unsigned int lsh   = shift - 12u;      /* 5 or 8 */
    const unsigned int lmask = (1u << lsh) - 1u;

    for (int i = tid; i < 4096; i += 256) s_hist[i] = 0u;
    __syncthreads();
    for (unsigned int i = tid; i < cnt; i += 256) {
        unsigned int fo = fordu(g_inbin[b][i]);
        atomicAdd(&s_hist[(fo >> lsh) & 0xFFFu], 1u);
    }
    __syncthreads();
    {
        unsigned int s = 0;
        int hi = 4095 - 16 * tid;
        #pragma unroll
        for (int i = 0; i < 16; i++) s += s_hist[hi - i];
        s_sum[tid] = s;
        __syncthreads();
        if (tid == 0) {
            unsigned int acc = 0;
            for (int j = 0; j < 256; j++) { s_pref[j] = acc; acc += s_sum[j]; }
        }
        __syncthreads();
        if (s_pref[tid] < rank && rank <= s_pref[tid] + s_sum[tid]) {
            unsigned int rem = rank - s_pref[tid];
            int hi2 = 4095 - 16 * tid;
            for (int i = 0; i < 16; i++) {
                unsigned int c = s_hist[hi2 - i];
                if (rem <= c) { s_sel = (unsigned)(hi2 - i); s_rank2 = rem; break; }
                rem -= c;
            }
        }
    }
    __syncthreads();
    const unsigned int sub = s_sel, rank2 = s_rank2;
    __syncthreads();

    if (tid < 256) s_hist[tid] = 0u;
    __syncthreads();
    for (unsigned int i = tid; i < cnt; i += 256) {
        unsigned int fo = fordu(g_inbin[b][i]);
        if (((fo >> lsh) & 0xFFFu) == sub) atomicAdd(&s_hist[fo & lmask], 1u);
    }
    __syncthreads();
    if (tid == 0) {
        unsigned int rem = rank2;
        int bin = (int)lmask;
        for (; bin >= 0; bin--) {
            unsigned int c = s_hist[bin];
            if (rem <= c) break;
            rem -= c;
        }
        unsigned int fo = (g_selpre[b] << shift) | (sub << lsh) | (unsigned int)bin;
        g_thr[b] = fordu_inv(fo);
    }
}

/* --------------- K5: per-batch top-5 + final output assembly -------------- */
__global__ __launch_bounds__(512) void k5_topk(float* __restrict__ out) {
    const int b = blockIdx.x;
    const int tid = threadIdx.x;
    __shared__ unsigned long long s_arr[512];
    __shared__ unsigned long long s_top[TOPK];
    __shared__ unsigned long long s_amax;

    unsigned int cnt = g_cand_cnt[b];
    if (cnt > CAND_CAP) cnt = CAND_CAP;
    const unsigned int thr_ord = fordu(g_thr[b]);

    unsigned long long loc[TOPK];
    unsigned long long amax = 0ull;
    #pragma unroll
    for (int j = 0; j < TOPK; j++) loc[j] = 0ull;
    for (unsigned int i = tid; i < cnt; i += 512) {
        unsigned long long k = g_cand[b][i];
        amax = umax64(amax, k);
        if ((unsigned int)(k >> 32) > thr_ord) {
            if (k > loc[TOPK - 1]) {
                loc[TOPK - 1] = k;
                #pragma unroll
                for (int j = TOPK - 1; j > 0; j--) {
                    if (loc[j] > loc[j - 1]) {
                        unsigned long long t = loc[j - 1]; loc[j - 1] = loc[j]; loc[j] = t;
                    }
                }
            }
        }
    }

    int ptr = 0;
    for (int r = 0; r < TOPK; r++) {
        s_arr[tid] = (ptr < TOPK) ? loc[ptr] : 0ull;
        __syncthreads();
        for (int o = 256; o; o >>= 1) {
            if (tid < o) s_arr[tid] = umax64(s_arr[tid], s_arr[tid + o]);
            __syncthreads();
        }
        unsigned long long w = s_arr[0];
        __syncthreads();
        if (tid == 0) s_top[r] = w;
        if (ptr < TOPK && loc[ptr] == w && w != 0ull) ptr++;
        __syncthreads();
    }

    /* block-reduce amax (global argmax = max candidate) */
    s_arr[tid] = amax;
    __syncthreads();
    for (int o = 256; o; o >>= 1) {
        if (tid < o) s_arr[tid] = umax64(s_arr[tid], s_arr[tid + o]);
        __syncthreads();
    }
    if (tid == 0) s_amax = s_arr[0];
    __syncthreads();

    if (tid == 0) {
        float topv[TOPK], xs[TOPK], ys[TOPK];
        bool hp[TOPK];
        #pragma unroll
        for (int j = 0; j < TOPK; j++) {
            unsigned long long k = s_top[j];
            hp[j] = (k != 0ull);
            topv[j] = hp[j] ? fordu_inv((unsigned int)(k >> 32)) : NEG_INF;
            unsigned int idx = 0xFFFFFFFFu - (unsigned int)(k & 0xFFFFFFFFull);
            xs[j] = (float)(idx % Wdim);
            ys[j] = (float)(idx / Wdim);
        }
        bool has_any = hp[0];
        if (!has_any) {
            unsigned int fidx = 0xFFFFFFFFu - (unsigned int)(s_amax & 0xFFFFFFFFull);
            xs[0] = (float)(fidx % Wdim);
            ys[0] = (float)(fidx / Wdim);
        }
        float peak_max = topv[0];
        int n_valid = 0;
        #pragma unroll
        for (int j = 0; j < TOPK; j++)
            if (topv[j] >= peak_max * 0.5f && hp[j]) n_valid++;
        if (n_valid < 1) n_valid = 1;
        #pragma unroll
        for (int j = 0; j < TOPK; j++) {
            bool keep = (j < n_valid);
            out[b * (TOPK * 2) + 2 * j + 0] = keep ? xs[j] : -1.0f;
            out[b * (TOPK * 2) + 2 * j + 1] = keep ? ys[j] : -1.0f;
            out[BATCH * TOPK * 2 + b * TOPK + j] = keep ? 1.0f : -1.0f;
        }
    }
}

/* -------------------------------- launch ---------------------------------- */
extern "C" void kernel_launch(void* const* d_in, const int* in_sizes, int n_in,
                              void* d_out, int out_size) {
    const float* in = (const float*)d_in[0];
    float* out = (float*)d_out;
    (void)in_sizes; (void)n_in; (void)out_size;

    k0_zero<<<256, 256>>>();
    k1_main<<<dim3(Wdim / TX, Hdim / TY, BATCH), 256>>>(in);
    k2_select<<<BATCH, 32>>>();
    kfb_hist<<<dim3(64, BATCH), 256>>>(in);
    kfb_select<<<BATCH, 256>>>();
    k3_compact<<<dim3(NPB / 4096, BATCH), 256>>>(in);
    k4_refine<<<BATCH, 256>>>();
    k5_topk<<<BATCH, 512>>>(out);
}

// round 4
// speedup vs baseline: 4.1292x; 1.4444x over previous
#include <cuda_runtime.h>
#include <stdint.h>

#define BATCH 16
#define Hdim 1024
#define Wdim 1024
#define NPB (Hdim*Wdim)
#define KTHR 104857
#define TOPK 5
#define CAND_CAP 65536

#define TX 128
#define TY 32
#define HALO 4
#define INW (TX + 2*HALO)
#define INH (TY + 2*HALO)
#define PIN 140
#define PRM 132
#define CBUF 512

#define PRE_L2 766u            /* (fordu(v)>>22) for v in [1.0,1.5) */
#define FO_GE15 0xBFC00000u    /* fordu(1.5) */

/* ------------ scratch ------------- */
__device__ unsigned long long g_cand[BATCH][CAND_CAP];
__device__ unsigned int       g_cand_cnt[BATCH];
__device__ unsigned int       g_cntS[BATCH];         /* count v>=1.5 */
__device__ unsigned int       g_ctrC[BATCH][32];     /* 32 bins over [1,1.5) */
__device__ int                g_fb[BATCH];
__device__ unsigned int       g_shift[BATCH];
__device__ unsigned int       g_selpre[BATCH];
__device__ unsigned int       g_rank[BATCH];
__device__ float              g_inbin[BATCH][NPB];
__device__ unsigned int       g_inbin_cnt[BATCH];
__device__ float              g_thr[BATCH];

__device__ __forceinline__ unsigned int fordu(float f) {
    unsigned int u = __float_as_uint(f);
    return u ^ (unsigned int)(((int)u >> 31) | (int)0x80000000);
}
__device__ __forceinline__ float fordu_inv(unsigned int v) {
    unsigned int u = (v & 0x80000000u) ? (v ^ 0x80000000u) : ~v;
    return __uint_as_float(u);
}
__device__ __forceinline__ unsigned long long umax64(unsigned long long a, unsigned long long b) {
    return a > b ? a : b;
}
#define NEG_INF __int_as_float(0xff800000)

/* ------------------------------- K0: zero -------------------------------- */
__global__ void k0_zero() {
    int tid = blockIdx.x * blockDim.x + threadIdx.x;
    if (tid < BATCH * 32) ((unsigned int*)g_ctrC)[tid] = 0u;
    if (tid < BATCH) {
        g_cand_cnt[tid]  = 0u;
        g_inbin_cnt[tid] = 0u;
        g_cntS[tid]      = 0u;
    }
}

/* --------- K1: max filter + counting + peak candidates ---------- */
__global__ __launch_bounds__(256) void k1_main(const float* __restrict__ in) {
    __shared__ __align__(16) float s_in[INH * PIN];
    __shared__ __align__(16) float s_rm[INH * PRM];
    __shared__ unsigned long long s_cbuf[CBUF];
    __shared__ unsigned int s_ccnt, s_cbase, s_cn;
    __shared__ unsigned int s_c32[8][32];
    __shared__ unsigned int s_red[8];

    const int b   = blockIdx.z;
    const int tx0 = blockIdx.x * TX;
    const int ty0 = blockIdx.y * TY;
    const float* base = in + (size_t)b * NPB;
    const int tid  = threadIdx.x;
    const int lane = tid & 31;
    const int wid  = tid >> 5;

    if (tid < 8)  { s_red[tid] = 0u; }
    if (tid == 0) { s_ccnt = 0u; }
    s_c32[wid][lane] = 0u;

    /* ---------------- load tile + halo ---------------- */
    const bool interior = (blockIdx.x > 0) && (blockIdx.x < (Wdim/TX - 1)) &&
                          (blockIdx.y > 0) && (blockIdx.y < (Hdim/TY - 1));
    if (interior) {
        const float4* gbase = (const float4*)(base + (size_t)(ty0 - HALO) * Wdim + (tx0 - HALO));
        #pragma unroll
        for (int ri = 0; ri < 5; ri++) {
            int r = wid + ri * 8;
            const float4* grow = gbase + (size_t)r * (Wdim / 4);
            float4* srow = (float4*)&s_in[r * PIN];
            srow[lane] = grow[lane];
            if (lane < 2) srow[32 + lane] = grow[32 + lane];
        }
    } else {
        #pragma unroll
        for (int ri = 0; ri < 5; ri++) {
            int r = wid + ri * 8;
            int gy = ty0 + r - HALO;
            bool rowin = (unsigned)gy < (unsigned)Hdim;
            #pragma unroll
            for (int ci = 0; ci < 5; ci++) {
                int c = lane + ci * 32;
                if (c < INW) {
                    int gx = tx0 + c - HALO;
                    float v = NEG_INF;
                    if (rowin && (unsigned)gx < (unsigned)Wdim) v = base[gy * Wdim + gx];
                    s_in[r * PIN + c] = v;
                }
            }
        }
    }
    __syncthreads();

    /* -------- hpass: warp-per-row, lane makes 4 outputs; counting fused ---- */
    unsigned int myS = 0u;
    #pragma unroll
    for (int it = 0; it < 5; it++) {
        int r = wid + it * 8;                 /* warp-uniform row 0..39 */
        const float4* rf4 = (const float4*)&s_in[r * PIN];
        float4 A = rf4[lane], B = rf4[lane + 1], C = rf4[lane + 2];
        float t[12] = {A.x,A.y,A.z,A.w, B.x,B.y,B.z,B.w, C.x,C.y,C.z,C.w};
        float m2[10], m4[8];
        #pragma unroll
        for (int i = 0; i < 10; i++) m2[i] = fmaxf(t[i], t[i + 1]);
        #pragma unroll
        for (int i = 0; i < 8; i++)  m4[i] = fmaxf(m2[i], m2[i + 2]);
        float4 o;
        o.x = fmaxf(fmaxf(m4[0], m4[4]), t[8]);
        o.y = fmaxf(fmaxf(m4[1], m4[5]), t[9]);
        o.z = fmaxf(fmaxf(m4[2], m4[6]), t[10]);
        o.w = fmaxf(fmaxf(m4[3], m4[7]), t[11]);
        ((float4*)&s_rm[r * PRM])[lane] = o;

        /* counting on the 4 center (interior) elements t[4..7] */
        if (r >= HALO && r < HALO + TY) {
            #pragma unroll
            for (int j = 4; j < 8; j++) {
                unsigned int fo = fordu(t[j]);
                if (fo >= FO_GE15) myS++;
                if ((fo >> 22) == PRE_L2) atomicAdd(&s_c32[wid][(fo >> 17) & 31u], 1u);
            }
        }
    }
    /* reduce cntS */
    #pragma unroll
    for (int o = 16; o; o >>= 1) myS += __shfl_xor_sync(0xFFFFFFFFu, myS, o);
    if (lane == 0) s_red[wid] = myS;
    __syncthreads();

    if (tid == 0) {
        unsigned int s = 0;
        #pragma unroll
        for (int w = 0; w < 8; w++) s += s_red[w];
        if (s) atomicAdd(&g_cntS[b], s);
    }
    if (tid < 32) {
        unsigned int s = 0;
        #pragma unroll
        for (int w = 0; w < 8; w++) s += s_c32[w][tid];
        if (s) atomicAdd(&g_ctrC[b][tid], s);
    }

    /* -------- vpass: 9-window vertical max + peak detect ------------------ */
    for (int c = tid; c < (TY / 8) * TX; c += 256) {
        int x  = c & 127;
        int yc = (c >> 7) << 3;
        float t[16];
        #pragma unroll
        for (int i = 0; i < 16; i++) t[i] = s_rm[(yc + i) * PRM + x];
        float m2[15], m4[13], m8[9];
        #pragma unroll
        for (int i = 0; i < 15; i++) m2[i] = fmaxf(t[i], t[i + 1]);
        #pragma unroll
        for (int i = 0; i < 13; i++) m4[i] = fmaxf(m2[i], m2[i + 2]);
        #pragma unroll
        for (int i = 0; i < 9; i++)  m8[i] = fmaxf(m4[i], m4[i + 4]);
        #pragma unroll
        for (int j = 0; j < 8; j++) {
            float lm = fmaxf(m8[j], t[j + 8]);
            float v  = s_in[(yc + j + HALO) * PIN + x + HALO];
            if (v == lm) {
                unsigned int idx = (unsigned)(ty0 + yc + j) * Wdim + (unsigned)(tx0 + x);
                unsigned long long key =
                    ((unsigned long long)fordu(v) << 32) | (unsigned long long)(0xFFFFFFFFu - idx);
                unsigned int p = atomicAdd(&s_ccnt, 1u);
                if (p < CBUF) s_cbuf[p] = key;
                else {
                    unsigned int q = atomicAdd(&g_cand_cnt[b], 1u);
                    if (q < CAND_CAP) g_cand[b][q] = key;
                }
            }
        }
    }
    __syncthreads();

    if (tid == 0) {
        unsigned int n = s_ccnt < CBUF ? s_ccnt : CBUF;
        s_cn = n;
        s_cbase = atomicAdd(&g_cand_cnt[b], n);
    }
    __syncthreads();
    for (unsigned int i = tid; i < s_cn; i += 256) {
        unsigned int q = s_cbase + i;
        if (q < CAND_CAP) g_cand[b][q] = s_cbuf[i];
    }
}

/* ---------- K2: locate rank among 32 bins of [1,1.5), else fallback ------- */
__global__ void k2_select() {
    const int b = blockIdx.x;
    __shared__ unsigned int c[32];
    if (threadIdx.x < 32) c[threadIdx.x] = g_ctrC[b][threadIdx.x];
    __syncwarp();
    if (threadIdx.x == 0) {
        unsigned int S = g_cntS[b];
        unsigned int cum = S;
        int sel = -1; unsigned int rem = 0;
        for (int j = 31; j >= 0; j--) {
            if (cum < (unsigned)KTHR && (unsigned)KTHR <= cum + c[j]) {
                sel = j; rem = (unsigned)KTHR - cum; break;
            }
            cum += c[j];
        }
        if (sel < 0) g_fb[b] = 1;
        else {
            g_fb[b] = 0;
            g_shift[b]  = 17u;
            g_selpre[b] = (PRE_L2 << 5) | (unsigned)sel;
            g_rank[b]   = rem;
        }
    }
}

/* -------- KFB: fallback histogram+select, one block/batch, early-exit ----- */
__global__ __launch_bounds__(1024) void kfb_all(const float* __restrict__ in) {
    const int b = blockIdx.x;
    if (!g_fb[b]) return;
    __shared__ unsigned int s_hist[4096];
    __shared__ unsigned int s_sum[256];
    __shared__ unsigned int s_pref[256];
    const int tid = threadIdx.x;
    for (int i = tid; i < 4096; i += 1024) s_hist[i] = 0u;
    __syncthreads();
    const float4* base = (const float4*)(in + (size_t)b * NPB);
    for (int j = 0; j < 256; j++) {
        float4 v = base[tid + 1024 * j];
        atomicAdd(&s_hist[fordu(v.x) >> 20], 1u);
        atomicAdd(&s_hist[fordu(v.y) >> 20], 1u);
        atomicAdd(&s_hist[fordu(v.z) >> 20], 1u);
        atomicAdd(&s_hist[fordu(v.w) >> 20], 1u);
    }
    __syncthreads();
    if (tid < 256) {
        unsigned int s = 0;
        int hi = 4095 - 16 * tid;
        #pragma unroll
        for (int i = 0; i < 16; i++) s += s_hist[hi - i];
        s_sum[tid] = s;
    }
    __syncthreads();
    if (tid == 0) {
        unsigned int acc = 0;
        for (int j = 0; j < 256; j++) { s_pref[j] = acc; acc += s_sum[j]; }
    }
    __syncthreads();
    if (tid < 256 && s_pref[tid] < (unsigned)KTHR && (unsigned)KTHR <= s_pref[tid] + s_sum[tid]) {
        unsigned int rem = (unsigned)KTHR - s_pref[tid];
        int hi2 = 4095 - 16 * tid;
        for (int i = 0; i < 16; i++) {
            unsigned int c = s_hist[hi2 - i];
            if (rem <= c) {
                g_selpre[b] = (unsigned)(hi2 - i);
                g_shift[b]  = 20u;
                g_rank[b]   = rem;
                break;
            }
            rem -= c;
        }
    }
}

/* ------------------ K3: compact elements of selected bin ------------------ */
__global__ __launch_bounds__(256) void k3_compact(const float* __restrict__ in) {
    __shared__ float s_buf[4096];
    __shared__ unsigned int s_cnt, s_base, s_n;

    const int b = blockIdx.y;
    const unsigned int selpre = g_selpre[b];
    const unsigned int shift  = g_shift[b];
    const unsigned int hb     = 0x80000000u >> shift;
    const unsigned int target = (selpre & hb) ? (selpre ^ hb)
                                              : ((~selpre) & (0xFFFFFFFFu >> shift));
    const float4* base = (const float4*)(in + (size_t)b * NPB);
    const int tid = threadIdx.x;
    if (tid == 0) s_cnt = 0u;
    __syncthreads();

    const int blk4 = blockIdx.x * 1024;
    float4 v[4];
    #pragma unroll
    for (int k = 0; k < 4; k++) v[k] = base[blk4 + tid + 256 * k];

    #pragma unroll
    for (int k = 0; k < 4; k++) {
        float a[4] = {v[k].x, v[k].y, v[k].z, v[k].w};
        #pragma unroll
        for (int j = 0; j < 4; j++) {
            if ((__float_as_uint(a[j]) >> shift) == target) {
                unsigned int p = atomicAdd(&s_cnt, 1u);
                s_buf[p] = a[j];
            }
        }
    }
    __syncthreads();

    if (tid == 0) {
        s_n = s_cnt;
        s_base = atomicAdd(&g_inbin_cnt[b], s_cnt);
    }
    __syncthreads();
    for (unsigned int i = tid; i < s_n; i += 256)
        g_inbin[b][s_base + i] = s_buf[i];
}

/* -------- K4: refine remaining bits (12 then shift-12) -> exact thr ------- */
__global__ __launch_bounds__(256) void k4_refine() {
    const int b = blockIdx.x;
    const int tid = threadIdx.x;
    __shared__ unsigned int s_hist[4096];
    __shared__ unsigned int s_sum[256];
    __shared__ unsigned int s_pref[256];
    __shared__ unsigned int s_sel, s_rank2;

    const unsigned int cnt   = g_inbin_cnt[b];
    const unsigned int rank  = g_rank[b];
    const unsigned int shift = g_shift[b];
    const unsigned int lsh   = shift - 12u;      /* 5 or 8 */
    const unsigned int lmask = (1u << lsh) - 1u;

    for (int i = tid; i < 4096; i += 256) s_hist[i] = 0u;
    __syncthreads();
    for (unsigned int i = tid; i < cnt; i += 256) {
        unsigned int fo = fordu(g_inbin[b][i]);
        atomicAdd(&s_hist[(fo >> lsh) & 0xFFFu], 1u);
    }
    __syncthreads();
    {
        unsigned int s = 0;
        int hi = 4095 - 16 * tid;
        #pragma unroll
        for (int i = 0; i < 16; i++) s += s_hist[hi - i];
        s_sum[tid] = s;
        __syncthreads();
        if (tid == 0) {
            unsigned int acc = 0;
            for (int j = 0; j < 256; j++) { s_pref[j] = acc; acc += s_sum[j]; }
        }
        __syncthreads();
        if (s_pref[tid] < rank && rank <= s_pref[tid] + s_sum[tid]) {
            unsigned int rem = rank - s_pref[tid];
            int hi2 = 4095 - 16 * tid;
            for (int i = 0; i < 16; i++) {
                unsigned int c = s_hist[hi2 - i];
                if (rem <= c) { s_sel = (unsigned)(hi2 - i); s_rank2 = rem; break; }
                rem -= c;
            }
        }
    }
    __syncthreads();
    const unsigned int sub = s_sel, rank2 = s_rank2;
    __syncthreads();

    if (tid < 256) s_hist[tid] = 0u;
    __syncthreads();
    for (unsigned int i = tid; i < cnt; i += 256) {
        unsigned int fo = fordu(g_inbin[b][i]);
        if (((fo >> lsh) & 0xFFFu) == sub) atomicAdd(&s_hist[fo & lmask], 1u);
    }
    __syncthreads();
    if (tid == 0) {
        unsigned int rem = rank2;
        int bin = (int)lmask;
        for (; bin >= 0; bin--) {
            unsigned int c = s_hist[bin];
            if (rem <= c) break;
            rem -= c;
        }
        unsigned int fo = (g_selpre[b] << shift) | (sub << lsh) | (unsigned int)bin;
        g_thr[b] = fordu_inv(fo);
    }
}

/* --------------- K5: per-batch top-5 + final output assembly -------------- */
__global__ __launch_bounds__(512) void k5_topk(float* __restrict__ out) {
    const int b = blockIdx.x;
    const int tid = threadIdx.x;
    __shared__ unsigned long long s_arr[512];
    __shared__ unsigned long long s_top[TOPK];
    __shared__ unsigned long long s_amax;

    unsigned int cnt = g_cand_cnt[b];
    if (cnt > CAND_CAP) cnt = CAND_CAP;
    const unsigned int thr_ord = fordu(g_thr[b]);

    unsigned long long loc[TOPK];
    unsigned long long amax = 0ull;
    #pragma unroll
    for (int j = 0; j < TOPK; j++) loc[j] = 0ull;
    for (unsigned int i = tid; i < cnt; i += 512) {
        unsigned long long k = g_cand[b][i];
        amax = umax64(amax, k);
        if ((unsigned int)(k >> 32) > thr_ord) {
            if (k > loc[TOPK - 1]) {
                loc[TOPK - 1] = k;
                #pragma unroll
                for (int j = TOPK - 1; j > 0; j--) {
                    if (loc[j] > loc[j - 1]) {
                        unsigned long long t = loc[j - 1]; loc[j - 1] = loc[j]; loc[j] = t;
                    }
                }
            }
        }
    }

    int ptr = 0;
    for (int r = 0; r < TOPK; r++) {
        s_arr[tid] = (ptr < TOPK) ? loc[ptr] : 0ull;
        __syncthreads();
        for (int o = 256; o; o >>= 1) {
            if (tid < o) s_arr[tid] = umax64(s_arr[tid], s_arr[tid + o]);
            __syncthreads();
        }
        unsigned long long w = s_arr[0];
        __syncthreads();
        if (tid == 0) s_top[r] = w;
        if (ptr < TOPK && loc[ptr] == w && w != 0ull) ptr++;
        __syncthreads();
    }

    s_arr[tid] = amax;
    __syncthreads();
    for (int o = 256; o; o >>= 1) {
        if (tid < o) s_arr[tid] = umax64(s_arr[tid], s_arr[tid + o]);
        __syncthreads();
    }
    if (tid == 0) s_amax = s_arr[0];
    __syncthreads();

    if (tid == 0) {
        float topv[TOPK], xs[TOPK], ys[TOPK];
        bool hp[TOPK];
        #pragma unroll
        for (int j = 0; j < TOPK; j++) {
            unsigned long long k = s_top[j];
            hp[j] = (k != 0ull);
            topv[j] = hp[j] ? fordu_inv((unsigned int)(k >> 32)) : NEG_INF;
            unsigned int idx = 0xFFFFFFFFu - (unsigned int)(k & 0xFFFFFFFFull);
            xs[j] = (float)(idx % Wdim);
            ys[j] = (float)(idx / Wdim);
        }
        bool has_any = hp[0];
        if (!has_any) {
            unsigned int fidx = 0xFFFFFFFFu - (unsigned int)(s_amax & 0xFFFFFFFFull);
            xs[0] = (float)(fidx % Wdim);
            ys[0] = (float)(fidx / Wdim);
        }
        float peak_max = topv[0];
        int n_valid = 0;
        #pragma unroll
        for (int j = 0; j < TOPK; j++)
            if (topv[j] >= peak_max * 0.5f && hp[j]) n_valid++;
        if (n_valid < 1) n_valid = 1;
        #pragma unroll
        for (int j = 0; j < TOPK; j++) {
            bool keep = (j < n_valid);
            out[b * (TOPK * 2) + 2 * j + 0] = keep ? xs[j] : -1.0f;
            out[b * (TOPK * 2) + 2 * j + 1] = keep ? ys[j] : -1.0f;
            out[BATCH * TOPK * 2 + b * TOPK + j] = keep ? 1.0f : -1.0f;
        }
    }
}

/* -------------------------------- launch ---------------------------------- */
extern "C" void kernel_launch(void* const* d_in, const int* in_sizes, int n_in,
                              void* d_out, int out_size) {
    const float* in = (const float*)d_in[0];
    float* out = (float*)d_out;
    (void)in_sizes; (void)n_in; (void)out_size;

    k0_zero<<<2, 512>>>();
    k1_main<<<dim3(Wdim / TX, Hdim / TY, BATCH), 256>>>(in);
    k2_select<<<BATCH, 32>>>();
    kfb_all<<<BATCH, 1024>>>(in);
    k3_compact<<<dim3(NPB / 4096, BATCH), 256>>>(in);
    k4_refine<<<BATCH, 256>>>();
    k5_topk<<<BATCH, 512>>>(out);
}